// round 4
// baseline (speedup 1.0000x reference)
#include <cuda_runtime.h>
#include <cuda_bf16.h>
#include <math.h>
#include <stdint.h>

// Problem shape (fixed)
#define B_  32
#define Ls  512
#define D_  768
#define Kp  8192
#define M_  (B_ * Ls)        // 16384

// ---------------- device scratch (allocation-free) -------------------------
__device__ float g_logits[(size_t)M_ * Kp];           // 512 MB fp32 logits
__device__ float g_c[M_];                             // per-row m + log(sum exp)
__device__ __nv_bfloat16 g_Qh[(size_t)M_ * D_];
__device__ __nv_bfloat16 g_Ql[(size_t)M_ * D_];
__device__ __nv_bfloat16 g_Ph[(size_t)Kp * D_];
__device__ __nv_bfloat16 g_Pl[(size_t)Kp * D_];

// ---------------- PTX helpers ------------------------------------------------
__device__ __forceinline__ uint32_t smem_u32(const void* p) {
    uint32_t a;
    asm("{ .reg .u64 t; cvta.to.shared.u64 t, %1; cvt.u32.u64 %0, t; }"
        : "=r"(a) : "l"(p));
    return a;
}
__device__ __forceinline__ void cp16(uint32_t dst, const void* src) {
    asm volatile("cp.async.cg.shared.global [%0], [%1], 16;" :: "r"(dst), "l"(src));
}
__device__ __forceinline__ void cp_commit() {
    asm volatile("cp.async.commit_group;" ::: "memory");
}
__device__ __forceinline__ void ldm_x4(uint32_t* r, uint32_t addr) {
    asm volatile("ldmatrix.sync.aligned.m8n8.x4.shared.b16 {%0,%1,%2,%3}, [%4];"
                 : "=r"(r[0]), "=r"(r[1]), "=r"(r[2]), "=r"(r[3]) : "r"(addr));
}
__device__ __forceinline__ void mma16816(float* c, const uint32_t* a, const uint32_t* b) {
    asm volatile(
        "mma.sync.aligned.m16n8k16.row.col.f32.bf16.bf16.f32 "
        "{%0,%1,%2,%3}, {%4,%5,%6,%7}, {%8,%9}, {%0,%1,%2,%3};"
        : "+f"(c[0]), "+f"(c[1]), "+f"(c[2]), "+f"(c[3])
        : "r"(a[0]), "r"(a[1]), "r"(a[2]), "r"(a[3]), "r"(b[0]), "r"(b[1]));
}

// ---------------- split fp32 -> bf16 hi/lo ----------------------------------
__global__ __launch_bounds__(256)
void split_kernel(const float* __restrict__ src, __nv_bfloat16* __restrict__ hi,
                  __nv_bfloat16* __restrict__ lo, int n)
{
    int i = blockIdx.x * 256 + threadIdx.x;
    if (i < n) {
        float v = src[i];
        __nv_bfloat16 h = __float2bfloat16(v);
        hi[i] = h;
        lo[i] = __float2bfloat16(v - __bfloat162float(h));
    }
}

// ---------------- HMMA GEMM: logits = (Q . P^T) / temp ---------------------
// CTA tile 128x256, K-chunk 32, 8 warps (2m x 4n), warp tile 64x64.
// bf16x3: acc += ah*bh + ah*bl + al*bh  (fp32 accumulate). 3-stage cp.async.
#define TILE_M 128
#define TILE_N 256
#define BK     32
#define CHUNKS (D_ / BK)            // 24
#define RSTRIDE 40                  // bf16 elems per smem row (80 B padded)
#define ROWB    (RSTRIDE * 2)       // 80
#define A_BYTES (128 * ROWB)        // 10240
#define B_BYTES (256 * ROWB)        // 20480
#define OFF_AH  0
#define OFF_AL  A_BYTES
#define OFF_BH  (2 * A_BYTES)
#define OFF_BL  (2 * A_BYTES + B_BYTES)
#define STAGE_BYTES (2 * A_BYTES + 2 * B_BYTES)   // 61440
#define NSTAGE  3
#define SMEM_GEMM (NSTAGE * STAGE_BYTES)          // 184320

__global__ __launch_bounds__(256, 1)
void gemm_mma(const float* __restrict__ temp)
{
    extern __shared__ __align__(16) char smem[];
    const uint32_t sb = smem_u32(smem);

    const int tid  = threadIdx.x;
    const int wid  = tid >> 5, lane = tid & 31;
    const int wm   = wid & 1;          // 0..1  -> 64-row m slot
    const int wn   = wid >> 1;         // 0..3  -> 64-col n slot
    const int m0   = blockIdx.x * TILE_M;
    const int n0   = blockIdx.y * TILE_N;

    // ---- async tile loader: chunk c into stage (c % 3) ----
    auto load_chunk = [&](int c) {
        const uint32_t stage = sb + (uint32_t)(c % NSTAGE) * STAGE_BYTES;
        const int kd0 = c * BK;
        // 3072 cp16 per chunk, 12 per thread
#pragma unroll
        for (int it = 0; it < 12; it++) {
            int i = tid + it * 256;             // 0..3071
            uint32_t dst;
            const __nv_bfloat16* src;
            int r, q;
            if (i < 1024) {                     // A hi/lo: 512 each
                int half = i >> 9;              // 0:hi 1:lo
                int j = i & 511;
                r = j >> 2; q = j & 3;
                dst = stage + (half ? OFF_AL : OFF_AH) + r * ROWB + q * 16;
                src = (half ? g_Ql : g_Qh) + (size_t)(m0 + r) * D_ + kd0 + q * 8;
            } else {                            // B hi/lo: 1024 each
                int j = i - 1024;
                int half = j >> 10;             // 0:hi 1:lo
                j &= 1023;
                r = j >> 2; q = j & 3;
                dst = stage + (half ? OFF_BL : OFF_BH) + r * ROWB + q * 16;
                src = (half ? g_Pl : g_Ph) + (size_t)(n0 + r) * D_ + kd0 + q * 8;
            }
            cp16(dst, src);
        }
        cp_commit();
    };

    float acc[4][8][4];
#pragma unroll
    for (int i = 0; i < 4; i++)
#pragma unroll
        for (int j = 0; j < 8; j++)
#pragma unroll
            for (int v = 0; v < 4; v++) acc[i][j][v] = 0.f;

    load_chunk(0);
    load_chunk(1);
    load_chunk(2);

    for (int c = 0; c < CHUNKS; c++) {
        const int rem = CHUNKS - 1 - c;     // newer chunks still needed
        if (rem >= 2)
            asm volatile("cp.async.wait_group 2;" ::: "memory");
        else if (rem == 1)
            asm volatile("cp.async.wait_group 1;" ::: "memory");
        else
            asm volatile("cp.async.wait_group 0;" ::: "memory");
        __syncthreads();

        const uint32_t stage = sb + (uint32_t)(c % NSTAGE) * STAGE_BYTES;
        const uint32_t Ah = stage + OFF_AH;
        const uint32_t Al = stage + OFF_AL;
        const uint32_t Bh = stage + OFF_BH;
        const uint32_t Bl = stage + OFF_BL;

#pragma unroll
        for (int k16 = 0; k16 < BK; k16 += 16) {
            // ---- B fragments: 8 n8-tiles (64 cols), hi and lo ----
            uint32_t bh[16], bl[16];
            const uint32_t bcol = (uint32_t)((k16 + (((lane >> 3) & 1) << 3)) * 2);
            const uint32_t brow = (uint32_t)(wn * 64 + ((lane >> 4) << 3) + (lane & 7));
#pragma unroll
            for (int g = 0; g < 4; g++) {
                uint32_t boff = (brow + g * 16) * ROWB + bcol;
                ldm_x4(&bh[g * 4], Bh + boff);
                ldm_x4(&bl[g * 4], Bl + boff);
            }

            const uint32_t acol = (uint32_t)((k16 + ((lane >> 4) << 3)) * 2);
            const uint32_t arow = (uint32_t)(wm * 64 + (lane & 15));
#pragma unroll
            for (int mt = 0; mt < 4; mt++) {
                uint32_t ah[4], al[4];
                uint32_t aoff = (arow + mt * 16) * ROWB + acol;
                ldm_x4(ah, Ah + aoff);
                ldm_x4(al, Al + aoff);
#pragma unroll
                for (int nt = 0; nt < 8; nt++) {
                    const uint32_t* bhp = &bh[(nt >> 1) * 4 + (nt & 1) * 2];
                    const uint32_t* blp = &bl[(nt >> 1) * 4 + (nt & 1) * 2];
                    mma16816(acc[mt][nt], ah, bhp);
                    mma16816(acc[mt][nt], ah, blp);
                    mma16816(acc[mt][nt], al, bhp);
                }
            }
        }
        __syncthreads();
        if (c + NSTAGE < CHUNKS) load_chunk(c + NSTAGE);
    }

    // ---- epilogue: regs -> g_logits with 1/temp ----
    const float invT = 1.0f / temp[0];
    const int rbase = m0 + wm * 64 + (lane >> 2);
    const int cbase = n0 + wn * 64 + (lane & 3) * 2;
#pragma unroll
    for (int mt = 0; mt < 4; mt++) {
#pragma unroll
        for (int nt = 0; nt < 8; nt++) {
            float* p0 = &g_logits[(size_t)(rbase + mt * 16) * Kp + cbase + nt * 8];
            float* p1 = &g_logits[(size_t)(rbase + mt * 16 + 8) * Kp + cbase + nt * 8];
            float2 w0 = make_float2(acc[mt][nt][0] * invT, acc[mt][nt][1] * invT);
            float2 w1 = make_float2(acc[mt][nt][2] * invT, acc[mt][nt][3] * invT);
            *reinterpret_cast<float2*>(p0) = w0;
            *reinterpret_cast<float2*>(p1) = w1;
        }
    }
}

// ---------------- reductions -------------------------------------------------
__device__ __forceinline__ float warpMax(float v) {
#pragma unroll
    for (int o = 16; o; o >>= 1) v = fmaxf(v, __shfl_xor_sync(0xffffffffu, v, o));
    return v;
}
__device__ __forceinline__ float warpSum(float v) {
#pragma unroll
    for (int o = 16; o; o >>= 1) v += __shfl_xor_sync(0xffffffffu, v, o);
    return v;
}

__global__ __launch_bounds__(256)
void row_stats()
{
    const int row = blockIdx.x;
    const float* Lr = g_logits + (size_t)row * Kp;
    const int tid = threadIdx.x;
    __shared__ float sh[8];
    __shared__ float bc;

    float m = -INFINITY;
    for (int i = tid; i < Kp; i += 256) m = fmaxf(m, Lr[i]);
    m = warpMax(m);
    if ((tid & 31) == 0) sh[tid >> 5] = m;
    __syncthreads();
    if (tid == 0) {
        float t = sh[0];
#pragma unroll
        for (int w = 1; w < 8; w++) t = fmaxf(t, sh[w]);
        bc = t;
    }
    __syncthreads();
    m = bc;

    float s = 0.f;
    for (int i = tid; i < Kp; i += 256) s += expf(Lr[i] - m);
    s = warpSum(s);
    if ((tid & 31) == 0) sh[tid >> 5] = s;
    __syncthreads();
    if (tid == 0) {
        float t = 0.f;
#pragma unroll
        for (int w = 0; w < 8; w++) t += sh[w];
        g_c[row] = m + logf(t);
    }
}

__global__ __launch_bounds__(256)
void col_max(const int* __restrict__ mask, float* __restrict__ out)
{
    const int b   = blockIdx.y;
    const int k   = blockIdx.x * 256 + threadIdx.x;
    const int tid = threadIdx.x;

    __shared__ float cs[Ls];
    for (int l = tid; l < Ls; l += 256)
        cs[l] = mask[b * Ls + l] ? g_c[b * Ls + l] : INFINITY;
    __syncthreads();

    const float* base = g_logits + (size_t)b * Ls * Kp + k;
    float t = -INFINITY;
#pragma unroll 4
    for (int l = 0; l < Ls; l++)
        t = fmaxf(t, base[(size_t)l * Kp] - cs[l]);

    out[b * Kp + k] = expf(t);
}

__global__ __launch_bounds__(256)
void l2norm(float* __restrict__ out)
{
    const int b = blockIdx.x;
    float* o = out + b * Kp;
    const int tid = threadIdx.x;
    __shared__ float sh[8];
    __shared__ float bc;

    float s = 0.f;
    for (int i = tid; i < Kp; i += 256) { float v = o[i]; s = fmaf(v, v, s); }
    s = warpSum(s);
    if ((tid & 31) == 0) sh[tid >> 5] = s;
    __syncthreads();
    if (tid == 0) {
        float t = 0.f;
#pragma unroll
        for (int w = 0; w < 8; w++) t += sh[w];
        bc = 1.0f / fmaxf(sqrtf(t), 1e-12f);
    }
    __syncthreads();
    const float sc = bc;
    for (int i = tid; i < Kp; i += 256) o[i] *= sc;
}

// ---------------- launch ----------------------------------------------------
extern "C" void kernel_launch(void* const* d_in, const int* in_sizes, int n_in,
                              void* d_out, int out_size)
{
    const float* Q    = (const float*)d_in[0];   // (32,512,768)
    const float* P    = (const float*)d_in[1];   // (8192,768)
    const float* temp = (const float*)d_in[2];
    const int*   mask = (const int*)d_in[3];     // (32,512)
    float* out = (float*)d_out;                  // (32,8192)

    cudaFuncSetAttribute(gemm_mma, cudaFuncAttributeMaxDynamicSharedMemorySize,
                         SMEM_GEMM);

    __nv_bfloat16 *qh, *ql, *ph, *pl;
    cudaGetSymbolAddress((void**)&qh, g_Qh);
    cudaGetSymbolAddress((void**)&ql, g_Ql);
    cudaGetSymbolAddress((void**)&ph, g_Ph);
    cudaGetSymbolAddress((void**)&pl, g_Pl);

    const int nQ = M_ * D_, nP = Kp * D_;
    split_kernel<<<(nQ + 255) / 256, 256>>>(Q, qh, ql, nQ);
    split_kernel<<<(nP + 255) / 256, 256>>>(P, ph, pl, nP);

    dim3 gGemm(M_ / TILE_M, Kp / TILE_N);        // (128, 32)
    gemm_mma<<<gGemm, 256, SMEM_GEMM>>>(temp);

    row_stats<<<M_, 256>>>();
    dim3 gCol(Kp / 256, B_);
    col_max<<<gCol, 256>>>(mask, out);
    l2norm<<<B_, 256>>>(out);
}

// round 5
// speedup vs baseline: 2.1323x; 2.1323x over previous
#include <cuda_runtime.h>
#include <cuda_bf16.h>
#include <math.h>
#include <stdint.h>

// Problem shape (fixed)
#define B_  32
#define Ls  512
#define D_  768
#define Kp  8192
#define M_  (B_ * Ls)        // 16384

// ---------------- device scratch (allocation-free) -------------------------
__device__ float g_logits[(size_t)M_ * Kp];           // fp32 logits (compact rows)
__device__ float g_c[M_];                             // per-row m + log(sum exp)
__device__ __nv_bfloat16 g_Qh[(size_t)M_ * D_];
__device__ __nv_bfloat16 g_Ql[(size_t)M_ * D_];
__device__ __nv_bfloat16 g_Ph[(size_t)Kp * D_];
__device__ __nv_bfloat16 g_Pl[(size_t)Kp * D_];
__device__ int g_cnt[B_];            // valid per batch
__device__ int g_local[M_];          // within-batch exclusive prefix
__device__ int g_off[B_ + 2];        // [0..32] offsets; [32]=valid total; [33]=padded
__device__ int g_rowidx[M_];         // compact row -> original row

// ---------------- PTX helpers ------------------------------------------------
__device__ __forceinline__ uint32_t smem_u32(const void* p) {
    uint32_t a;
    asm("{ .reg .u64 t; cvta.to.shared.u64 t, %1; cvt.u32.u64 %0, t; }"
        : "=r"(a) : "l"(p));
    return a;
}
__device__ __forceinline__ void cp16(uint32_t dst, const void* src) {
    asm volatile("cp.async.cg.shared.global [%0], [%1], 16;" :: "r"(dst), "l"(src));
}
__device__ __forceinline__ void cp_commit() {
    asm volatile("cp.async.commit_group;" ::: "memory");
}
__device__ __forceinline__ void ldm_x4(uint32_t* r, uint32_t addr) {
    asm volatile("ldmatrix.sync.aligned.m8n8.x4.shared.b16 {%0,%1,%2,%3}, [%4];"
                 : "=r"(r[0]), "=r"(r[1]), "=r"(r[2]), "=r"(r[3]) : "r"(addr));
}
__device__ __forceinline__ void mma16816(float* c, const uint32_t* a, const uint32_t* b) {
    asm volatile(
        "mma.sync.aligned.m16n8k16.row.col.f32.bf16.bf16.f32 "
        "{%0,%1,%2,%3}, {%4,%5,%6,%7}, {%8,%9}, {%0,%1,%2,%3};"
        : "+f"(c[0]), "+f"(c[1]), "+f"(c[2]), "+f"(c[3])
        : "r"(a[0]), "r"(a[1]), "r"(a[2]), "r"(a[3]), "r"(b[0]), "r"(b[1]));
}

// ---------------- mask compaction -------------------------------------------
__global__ __launch_bounds__(Ls)
void mask_scan(const int* __restrict__ mask)
{
    const int b = blockIdx.x, l = threadIdx.x;
    const int lane = l & 31, w = l >> 5;
    const int v = mask[b * Ls + l] ? 1 : 0;
    const unsigned bal = __ballot_sync(0xffffffffu, v);
    const int pre = __popc(bal & ((1u << lane) - 1u));
    __shared__ int ws[16];
    if (lane == 0) ws[w] = __popc(bal);
    __syncthreads();
    int woff = 0;
#pragma unroll
    for (int i = 0; i < 16; i++) woff += (i < w) ? ws[i] : 0;
    g_local[b * Ls + l] = woff + pre;
    if (l == Ls - 1) g_cnt[b] = woff + pre + v;
}

__global__ void scan_offsets()
{
    // single warp exclusive scan of 32 counts
    const int t = threadIdx.x;            // 0..31
    int v = g_cnt[t];
    int x = v;
#pragma unroll
    for (int o = 1; o < 32; o <<= 1) {
        int y = __shfl_up_sync(0xffffffffu, x, o);
        if ((t & 31) >= o) x += y;
    }
    g_off[t + 1] = x;                     // inclusive -> off[t+1]
    if (t == 0) g_off[0] = 0;
    if (t == 31) g_off[B_ + 1] = (x + 127) & ~127;   // padded total
}

__global__ __launch_bounds__(Ls)
void scatter_idx(const int* __restrict__ mask)
{
    const int b = blockIdx.x, l = threadIdx.x;
    if (mask[b * Ls + l])
        g_rowidx[g_off[b] + g_local[b * Ls + l]] = b * Ls + l;
}

// ---------------- split Q (gather, 1/temp folded) + split P ----------------
__global__ __launch_bounds__(256)
void splitQ(const float* __restrict__ Q, const float* __restrict__ temp)
{
    const int cr = blockIdx.x;                 // compact row
    const int valid  = g_off[B_];
    const int padded = g_off[B_ + 1];
    if (cr >= padded) return;
    const int tid = threadIdx.x;
    __nv_bfloat16* hp = g_Qh + (size_t)cr * D_;
    __nv_bfloat16* lp = g_Ql + (size_t)cr * D_;
    if (cr >= valid) {
#pragma unroll
        for (int j = 0; j < 3; j++) {
            hp[tid + j * 256] = __float2bfloat16(0.f);
            lp[tid + j * 256] = __float2bfloat16(0.f);
        }
        return;
    }
    const float invT = 1.0f / temp[0];
    const float* src = Q + (size_t)g_rowidx[cr] * D_;
#pragma unroll
    for (int j = 0; j < 3; j++) {
        float v = src[tid + j * 256] * invT;
        __nv_bfloat16 h = __float2bfloat16(v);
        hp[tid + j * 256] = h;
        lp[tid + j * 256] = __float2bfloat16(v - __bfloat162float(h));
    }
}

__global__ __launch_bounds__(256)
void splitP(const float* __restrict__ src, int n)
{
    int i = blockIdx.x * 256 + threadIdx.x;
    if (i < n) {
        float v = src[i];
        __nv_bfloat16 h = __float2bfloat16(v);
        g_Ph[i] = h;
        g_Pl[i] = __float2bfloat16(v - __bfloat162float(h));
    }
}

// ---------------- HMMA GEMM (R3 proven config) ------------------------------
// CTA tile 128x128, K-chunk 32, 8 warps (2m x 4n), warp tile 64x32, 2 stages.
#define TILE_M 128
#define TILE_N 128
#define BK     32
#define CHUNKS (D_ / BK)       // 24
#define RSTRIDE 40
#define ROWB    (RSTRIDE * 2)
#define TILE_BYTES (128 * ROWB)             // 10240
#define STAGE_BYTES (4 * TILE_BYTES)        // Ah, Al, Bh, Bl
#define SMEM_GEMM   (2 * STAGE_BYTES)       // 81920

__global__ __launch_bounds__(256, 2)
void gemm_mma()
{
    if (blockIdx.x * TILE_M >= g_off[B_ + 1]) return;   // beyond padded rows

    extern __shared__ __align__(16) char smem[];
    const uint32_t sb = smem_u32(smem);

    const int tid  = threadIdx.x;
    const int wid  = tid >> 5, lane = tid & 31;
    const int wm   = wid & 1;
    const int wn   = wid >> 1;
    const int m0   = blockIdx.x * TILE_M;
    const int n0   = blockIdx.y * TILE_N;

    auto load_chunk = [&](int c) {
        const uint32_t stage = sb + (uint32_t)(c & 1) * STAGE_BYTES;
        const int kd0 = c * BK;
#pragma unroll
        for (int it = 0; it < 8; it++) {
            int i    = tid + it * 256;
            int tile = i >> 9;                  // 0:Ah 1:Al 2:Bh 3:Bl
            int r    = (i >> 2) & 127;
            int q    = i & 3;
            uint32_t dst = stage + (uint32_t)tile * TILE_BYTES + r * ROWB + q * 16;
            size_t ge = (size_t)((tile < 2 ? m0 : n0) + r) * D_ + kd0 + q * 8;
            const __nv_bfloat16* src =
                tile == 0 ? g_Qh : tile == 1 ? g_Ql : tile == 2 ? g_Ph : g_Pl;
            cp16(dst, src + ge);
        }
        cp_commit();
    };

    float acc[4][4][4];
#pragma unroll
    for (int i = 0; i < 4; i++)
#pragma unroll
        for (int j = 0; j < 4; j++)
#pragma unroll
            for (int v = 0; v < 4; v++) acc[i][j][v] = 0.f;

    load_chunk(0);
    load_chunk(1);

    for (int c = 0; c < CHUNKS; c++) {
        if (c + 1 < CHUNKS)
            asm volatile("cp.async.wait_group 1;" ::: "memory");
        else
            asm volatile("cp.async.wait_group 0;" ::: "memory");
        __syncthreads();

        const uint32_t stage = sb + (uint32_t)(c & 1) * STAGE_BYTES;
        const uint32_t Ah = stage;
        const uint32_t Al = stage + TILE_BYTES;
        const uint32_t Bh = stage + 2 * TILE_BYTES;
        const uint32_t Bl = stage + 3 * TILE_BYTES;

#pragma unroll
        for (int k16 = 0; k16 < BK; k16 += 16) {
            uint32_t boff = (uint32_t)((wn * 32 + ((lane >> 4) << 3) + (lane & 7)) * ROWB
                                       + (k16 + (((lane >> 3) & 1) << 3)) * 2);
            uint32_t bh[8], bl[8];
            ldm_x4(&bh[0], Bh + boff);
            ldm_x4(&bh[4], Bh + boff + 16 * ROWB);
            ldm_x4(&bl[0], Bl + boff);
            ldm_x4(&bl[4], Bl + boff + 16 * ROWB);

            uint32_t aoff = (uint32_t)((wm * 64 + (lane & 15)) * ROWB
                                       + (k16 + ((lane >> 4) << 3)) * 2);
#pragma unroll
            for (int mt = 0; mt < 4; mt++) {
                uint32_t ah[4], al[4];
                ldm_x4(ah, Ah + aoff + mt * 16 * ROWB);
                ldm_x4(al, Al + aoff + mt * 16 * ROWB);
#pragma unroll
                for (int nt = 0; nt < 4; nt++) {
                    mma16816(acc[mt][nt], ah, &bh[nt * 2]);
                    mma16816(acc[mt][nt], ah, &bl[nt * 2]);
                    mma16816(acc[mt][nt], al, &bh[nt * 2]);
                }
            }
        }
        __syncthreads();
        if (c + 2 < CHUNKS) load_chunk(c + 2);
    }

    const int rbase = m0 + wm * 64 + (lane >> 2);
    const int cbase = n0 + wn * 32 + (lane & 3) * 2;
#pragma unroll
    for (int mt = 0; mt < 4; mt++) {
#pragma unroll
        for (int nt = 0; nt < 4; nt++) {
            float* p0 = &g_logits[(size_t)(rbase + mt * 16) * Kp + cbase + nt * 8];
            float* p1 = &g_logits[(size_t)(rbase + mt * 16 + 8) * Kp + cbase + nt * 8];
            *reinterpret_cast<float2*>(p0) = make_float2(acc[mt][nt][0], acc[mt][nt][1]);
            *reinterpret_cast<float2*>(p1) = make_float2(acc[mt][nt][2], acc[mt][nt][3]);
        }
    }
}

// ---------------- reductions -------------------------------------------------
__device__ __forceinline__ float warpMax(float v) {
#pragma unroll
    for (int o = 16; o; o >>= 1) v = fmaxf(v, __shfl_xor_sync(0xffffffffu, v, o));
    return v;
}
__device__ __forceinline__ float warpSum(float v) {
#pragma unroll
    for (int o = 16; o; o >>= 1) v += __shfl_xor_sync(0xffffffffu, v, o);
    return v;
}

__global__ __launch_bounds__(256)
void row_stats()
{
    const int row = blockIdx.x;
    if (row >= g_off[B_]) return;                    // only valid compact rows
    const float* Lr = g_logits + (size_t)row * Kp;
    const int tid = threadIdx.x;
    __shared__ float sh[8];
    __shared__ float bc;

    float m = -INFINITY;
    for (int i = tid; i < Kp; i += 256) m = fmaxf(m, Lr[i]);
    m = warpMax(m);
    if ((tid & 31) == 0) sh[tid >> 5] = m;
    __syncthreads();
    if (tid == 0) {
        float t = sh[0];
#pragma unroll
        for (int w = 1; w < 8; w++) t = fmaxf(t, sh[w]);
        bc = t;
    }
    __syncthreads();
    m = bc;

    float s = 0.f;
    for (int i = tid; i < Kp; i += 256) s += expf(Lr[i] - m);
    s = warpSum(s);
    if ((tid & 31) == 0) sh[tid >> 5] = s;
    __syncthreads();
    if (tid == 0) {
        float t = 0.f;
#pragma unroll
        for (int w = 0; w < 8; w++) t += sh[w];
        g_c[row] = m + logf(t);
    }
}

__global__ __launch_bounds__(256)
void col_max(float* __restrict__ out)
{
    const int b   = blockIdx.y;
    const int k   = blockIdx.x * 256 + threadIdx.x;
    const int tid = threadIdx.x;
    const int lo  = g_off[b], hi = g_off[b + 1];
    const int cnt = hi - lo;

    __shared__ float cs[Ls];
    for (int i = tid; i < cnt; i += 256) cs[i] = g_c[lo + i];
    __syncthreads();

    const float* base = g_logits + (size_t)lo * Kp + k;
    float t = -INFINITY;
    for (int i = 0; i < cnt; i++)
        t = fmaxf(t, base[(size_t)i * Kp] - cs[i]);

    out[b * Kp + k] = (cnt > 0) ? expf(t) : 0.f;
}

__global__ __launch_bounds__(256)
void l2norm(float* __restrict__ out)
{
    const int b = blockIdx.x;
    float* o = out + b * Kp;
    const int tid = threadIdx.x;
    __shared__ float sh[8];
    __shared__ float bc;

    float s = 0.f;
    for (int i = tid; i < Kp; i += 256) { float v = o[i]; s = fmaf(v, v, s); }
    s = warpSum(s);
    if ((tid & 31) == 0) sh[tid >> 5] = s;
    __syncthreads();
    if (tid == 0) {
        float t = 0.f;
#pragma unroll
        for (int w = 0; w < 8; w++) t += sh[w];
        bc = 1.0f / fmaxf(sqrtf(t), 1e-12f);
    }
    __syncthreads();
    const float sc = bc;
    for (int i = tid; i < Kp; i += 256) o[i] *= sc;
}

// ---------------- launch ----------------------------------------------------
extern "C" void kernel_launch(void* const* d_in, const int* in_sizes, int n_in,
                              void* d_out, int out_size)
{
    const float* Q    = (const float*)d_in[0];   // (32,512,768)
    const float* P    = (const float*)d_in[1];   // (8192,768)
    const float* temp = (const float*)d_in[2];
    const int*   mask = (const int*)d_in[3];     // (32,512)
    float* out = (float*)d_out;                  // (32,8192)

    cudaFuncSetAttribute(gemm_mma, cudaFuncAttributeMaxDynamicSharedMemorySize,
                         SMEM_GEMM);

    mask_scan<<<B_, Ls>>>(mask);
    scan_offsets<<<1, 32>>>();
    scatter_idx<<<B_, Ls>>>(mask);

    splitQ<<<M_, 256>>>(Q, temp);
    const int nP = Kp * D_;
    splitP<<<(nP + 255) / 256, 256>>>(P, nP);

    dim3 gGemm(M_ / TILE_M, Kp / TILE_N);        // (128, 64); empty m-tiles exit
    gemm_mma<<<gGemm, 256, SMEM_GEMM>>>();

    row_stats<<<M_, 256>>>();
    dim3 gCol(Kp / 256, B_);
    col_max<<<gCol, 256>>>(out);
    l2norm<<<B_, 256>>>(out);
}